// round 15
// baseline (speedup 1.0000x reference)
#include <cuda_runtime.h>
#include <math.h>
#include <stdint.h>

#define N_MAX 10000
#define E_MAX 100000

// Scratch (no cudaMalloc allowed)
__device__ float g_q[N_MAX * 20];
__device__ float g_z[N_MAX];
__device__ float g_ex[E_MAX];
__device__ float g_v[(size_t)E_MAX * 40];

__device__ __forceinline__ uint32_t cvt_tf32(float x) {
    uint32_t r; asm("cvt.rna.tf32.f32 %0, %1;" : "=r"(r) : "f"(x)); return r;
}

// ---------------------------------------------------------------------------
// Kernel 0: per-node q projection, zero z and out
// ---------------------------------------------------------------------------
__global__ void __launch_bounds__(64) k_nodes(const float* __restrict__ node_ft,
                        const float* __restrict__ wqs, const float* __restrict__ wqv,
                        float* __restrict__ out, int N)
{
    int n = blockIdx.x * blockDim.x + threadIdx.x;
    if (n >= N) return;
    const float* x = node_ft + (size_t)n * 40;
    float xs[16], xv[24];
#pragma unroll
    for (int i = 0; i < 16; i++) xs[i] = x[i];
#pragma unroll
    for (int i = 0; i < 24; i++) xv[i] = x[16 + i];
    const float s0 = 0.25f, s1 = 0.35355339059327373f;
    float q[20];
#pragma unroll
    for (int o = 0; o < 8; o++) {
        float a = 0.f;
#pragma unroll
        for (int i = 0; i < 16; i++) a += xs[i] * wqs[i * 8 + o];
        q[o] = a * s0;
    }
#pragma unroll
    for (int o = 0; o < 4; o++)
#pragma unroll
        for (int c = 0; c < 3; c++) {
            float a = 0.f;
#pragma unroll
            for (int i = 0; i < 8; i++) a += xv[i * 3 + c] * wqv[i * 4 + o];
            q[8 + o * 3 + c] = a * s1;
        }
#pragma unroll
    for (int i = 0; i < 20; i++) g_q[(size_t)n * 20 + i] = q[i];
    g_z[n] = 0.f;
    float4 z4 = make_float4(0.f, 0.f, 0.f, 0.f);
#pragma unroll
    for (int i = 0; i < 10; i++)
        *reinterpret_cast<float4*>(&out[(size_t)n * 40 + i * 4]) = z4;
}

// ---------------------------------------------------------------------------
// Main kernel: persistent, 32 edges/tile, 1024 threads (32 warps),
//   mma.sync tf32 weight-gen spread over 30 warps (32 cols each),
//   B fragments register-resident; uniform epilogue one part per warp.
// W tile: [e][col 0..959], pitch 971 (odd, scalar access), column layout:
//   k: w1[16x8]@0 w2[8x8]@128 w3[16x4]@192 w4[8x4]@256 w5[8x4]@288
//   v(+320): w1[16x16]@0 w2[8x16]@256 w3[16x8]@384 w4[8x8]@512 w5[8x8]@576
// ---------------------------------------------------------------------------
#define SB_W    0          // 32 x 971
#define SB_HK   31072      // 32 x 33 (tf32 bits)
#define SB_HV   32128      // 32 x 33
#define SB_W1K  33184      // 512
#define SB_W1V  33696      // 512
#define SB_WDS  34208      // 64
#define SB_WDV  34272      // 16
#define SB_ES   34288      // 32 x 16
#define SB_SH   34800      // 32 x 4
#define SB_IX   34928      // 64 ints
#define SB_P    34992      // 32 x 97
#define SB_K    38096      // 32 x 21
#define SB_QR   38768      // 32 x 21
#define SMEM_FLOATS 39440
#define SMEM_BYTES (SMEM_FLOATS * 4)
#define WP 971

__global__ void __launch_bounds__(1024, 1) k_edges(
    const float* __restrict__ node_ft,
    const int* __restrict__ eidx,
    const float* __restrict__ edge_sh,
    const float* __restrict__ edge_sc,
    const float* __restrict__ fck_w1,
    const float* __restrict__ fck_w2,
    const float* __restrict__ fcv_w1,
    const float* __restrict__ fcv_w2,
    const float* __restrict__ wdot_s,
    const float* __restrict__ wdot_v,
    int E)
{
    extern __shared__ float sm[];
    const int tid  = threadIdx.x;
    const int wid  = tid >> 5;
    const int lane = tid & 31;

    // ---- startup: B fragments -> registers (30 warps x 32 cols) ----
    const bool isv = (wid >= 10);
    const int tq = lane >> 2, tr = lane & 3;
    uint32_t bfrag[4][4][2];
    if (wid < 30) {
        const float* W2 = isv ? fcv_w2 : fck_w2;
        const int pitch = isv ? 640 : 320;
        const int nbase = isv ? (wid - 10) * 32 : wid * 32;
#pragma unroll
        for (int nc = 0; nc < 4; nc++) {
            int n0 = nbase + nc * 8;
#pragma unroll
            for (int kc = 0; kc < 4; kc++) {
                bfrag[nc][kc][0] = cvt_tf32(__ldg(&W2[(kc * 8 + tr) * pitch + n0 + tq]));
                bfrag[nc][kc][1] = cvt_tf32(__ldg(&W2[(kc * 8 + tr + 4) * pitch + n0 + tq]));
            }
        }
    }
    if (tid < 512) sm[SB_W1K + tid] = fck_w1[tid];
    else           sm[SB_W1V + tid - 512] = fcv_w1[tid - 512];
    if (tid < 64) sm[SB_WDS + tid] = wdot_s[tid];
    if (tid < 16) sm[SB_WDV + tid] = wdot_v[tid];
    __syncthreads();

    const float ISQ32 = 0.17677669529663687f;
    const float ISQ24 = 0.2041241452319315f;
    const float ISQ3  = 0.5773502691896258f;
    const float ISQ2  = 0.7071067811865476f;

    int* ixs = (int*)(sm + SB_IX);
    int* ixr = (int*)(sm + SB_IX + 32);
    const int ntiles = (E + 31) >> 5;

    for (int t = blockIdx.x; t < ntiles; t += 148) {
        const int ebase = t << 5;

        // ---- stage edge data (32 edges) ----
        if (tid < 512) {
            int e = tid >> 4, i = tid & 15;
            int eg = min(ebase + e, E - 1);
            sm[SB_ES + tid] = edge_sc[(size_t)eg * 16 + i];
        } else if (tid < 576) {
            int f = tid - 512;
            int e = f & 31, which = f >> 5;
            int eg = min(ebase + e, E - 1);
            if (which == 0) ixs[e] = eidx[eg];
            else            ixr[e] = eidx[E + eg];
        } else if (tid < 704) {
            int f = tid - 576;
            int eg = min(ebase + (f >> 2), E - 1);
            sm[SB_SH + f] = edge_sh[(size_t)eg * 4 + (f & 3)];
        }
        __syncthreads();

        // ---- P1: prefetch nf gather (1 task/thread), hidden acts, stage q ----
        const int e_pf = tid >> 5, r_pf = tid & 31;
        float nfv0 = 0.f, nfv1 = 0.f, nfv2 = 0.f;
        {
            const float* nf = node_ft + (size_t)ixs[e_pf] * 40;
            if (r_pf < 16) nfv0 = __ldg(&nf[r_pf]);
            else if (r_pf < 24) {
                int i = r_pf - 16;
                nfv0 = __ldg(&nf[16 + i * 3]);
                nfv1 = __ldg(&nf[17 + i * 3]);
                nfv2 = __ldg(&nf[18 + i * 3]);
            }
        }
        uint32_t* HK = (uint32_t*)(sm + SB_HK);
        uint32_t* HV = (uint32_t*)(sm + SB_HV);
#pragma unroll
        for (int s = 0; s < 2; s++) {
            int task = tid + s * 1024;
            int e = task >> 6, jj = task & 63, j = jj & 31;
            const float* W1 = sm + ((jj < 32) ? SB_W1K : SB_W1V);
            const float* es = sm + SB_ES + e * 16;
            float a = 0.f;
#pragma unroll
            for (int i = 0; i < 16; i++) a += es[i] * W1[i * 32 + j];
            a *= 0.25f;
            float h = a / (1.f + expf(-a));
            uint32_t hb = cvt_tf32(h);
            if (jj < 32) HK[e * 33 + j] = hb;
            else         HV[e * 33 + j] = hb;
        }
        if (tid < 640) {
            int e2 = tid / 20, r2 = tid - e2 * 20;
            sm[SB_QR + e2 * 21 + r2] = g_q[(size_t)ixr[e2] * 20 + r2];
        }
        __syncthreads();

        // ---- P-feature build (1 task/thread) + P2 mma (30 warps) ----
        {
            float* Pe = sm + SB_P + e_pf * 97;
            if (r_pf < 16) {
                float shs = sm[SB_SH + e_pf * 4];
                Pe[r_pf]      = nfv0;
                Pe[44 + r_pf] = nfv0 * shs;
            } else if (r_pf < 24) {
                int i = r_pf - 16;
                float shv0 = sm[SB_SH + e_pf * 4 + 1];
                float shv1 = sm[SB_SH + e_pf * 4 + 2];
                float shv2 = sm[SB_SH + e_pf * 4 + 3];
                Pe[16 + 0 * 8 + i] = nfv0;
                Pe[16 + 1 * 8 + i] = nfv1;
                Pe[16 + 2 * 8 + i] = nfv2;
                Pe[60 + i] = (nfv0 * shv0 + nfv1 * shv1 + nfv2 * shv2) * ISQ3;
                Pe[68 + 0 * 8 + i] = (nfv1 * shv2 - nfv2 * shv1) * ISQ2;
                Pe[68 + 1 * 8 + i] = (nfv2 * shv0 - nfv0 * shv2) * ISQ2;
                Pe[68 + 2 * 8 + i] = (nfv0 * shv1 - nfv1 * shv0) * ISQ2;
            }
        }
        if (wid < 30) {
            const uint32_t* Hs = (const uint32_t*)(sm + (isv ? SB_HV : SB_HK));
            const int nbase = isv ? (wid - 10) * 32 : wid * 32;
            const int wcol0 = isv ? 320 + nbase : nbase;
#pragma unroll
            for (int emt = 0; emt < 2; emt++) {
                const int er0 = emt * 16;
                uint32_t a[4][4];
#pragma unroll
                for (int kc = 0; kc < 4; kc++) {
                    int k0 = kc * 8;
                    a[kc][0] = Hs[(er0 + tq) * 33 + k0 + tr];
                    a[kc][1] = Hs[(er0 + tq + 8) * 33 + k0 + tr];
                    a[kc][2] = Hs[(er0 + tq) * 33 + k0 + tr + 4];
                    a[kc][3] = Hs[(er0 + tq + 8) * 33 + k0 + tr + 4];
                }
#pragma unroll
                for (int nc = 0; nc < 4; nc++) {
                    float c0 = 0.f, c1 = 0.f, c2 = 0.f, c3 = 0.f;
#pragma unroll
                    for (int kc = 0; kc < 4; kc++) {
                        asm volatile(
                            "mma.sync.aligned.m16n8k8.row.col.f32.tf32.tf32.f32 "
                            "{%0,%1,%2,%3}, {%4,%5,%6,%7}, {%8,%9}, {%0,%1,%2,%3};"
                            : "+f"(c0), "+f"(c1), "+f"(c2), "+f"(c3)
                            : "r"(a[kc][0]), "r"(a[kc][1]), "r"(a[kc][2]), "r"(a[kc][3]),
                              "r"(bfrag[nc][kc][0]), "r"(bfrag[nc][kc][1]));
                    }
                    float* W = sm + SB_W;
                    int col = wcol0 + nc * 8 + 2 * tr;
                    W[(er0 + tq) * WP + col]         = c0 * ISQ32;
                    W[(er0 + tq) * WP + col + 1]     = c1 * ISQ32;
                    W[(er0 + tq + 8) * WP + col]     = c2 * ISQ32;
                    W[(er0 + tq + 8) * WP + col + 1] = c3 * ISQ32;
                }
            }
        }
        __syncthreads();

        // ---- P3: uniform epilogue, one part per warp, lane = edge ----
        {
            const int e = lane;
            const int part = wid;
            const int eg = ebase + e;
            const bool active = (eg < E);
            const float* Pe = sm + SB_P + e * 97;
            const float* Wt = sm + SB_W + e * WP;

            if (part < 8) {
                int o = part;
                float acc = 0.f;
#pragma unroll
                for (int i = 0; i < 16; i++) acc += Pe[44 + i] * Wt[i * 8 + o];
#pragma unroll
                for (int i = 0; i < 8;  i++) acc += Pe[60 + i] * Wt[128 + i * 8 + o];
                sm[SB_K + e * 21 + o] = acc * ISQ24;

                float acc2 = 0.f;
#pragma unroll
                for (int i = 0; i < 16; i++) acc2 += Pe[44 + i] * Wt[320 + i * 16 + o];
#pragma unroll
                for (int i = 0; i < 8;  i++) acc2 += Pe[60 + i] * Wt[576 + i * 16 + o];
                if (active) g_v[(size_t)eg * 40 + o] = acc2 * ISQ24;
            } else if (part < 20) {
                int tt = part - 8, o = tt / 3, c = tt - 3 * o;
                float shs  = sm[SB_SH + e * 4];
                float shvc = sm[SB_SH + e * 4 + 1 + c];
                float a = 0.f, b = 0.f, cx = 0.f;
#pragma unroll
                for (int i = 0; i < 16; i++) a  += Pe[i]              * Wt[192 + i * 4 + o];
#pragma unroll
                for (int i = 0; i < 8;  i++) b  += Pe[16 + c * 8 + i] * Wt[256 + i * 4 + o];
#pragma unroll
                for (int i = 0; i < 8;  i++) cx += Pe[68 + c * 8 + i] * Wt[288 + i * 4 + o];
                sm[SB_K + e * 21 + 8 + tt] = (shvc * a + shs * b + cx) * ISQ32;

                float a2 = 0.f, b2 = 0.f, cx2 = 0.f;
#pragma unroll
                for (int i = 0; i < 16; i++) a2  += Pe[i]              * Wt[704 + i * 8 + o];
#pragma unroll
                for (int i = 0; i < 8;  i++) b2  += Pe[16 + c * 8 + i] * Wt[832 + i * 8 + o];
#pragma unroll
                for (int i = 0; i < 8;  i++) cx2 += Pe[68 + c * 8 + i] * Wt[896 + i * 8 + o];
                if (active) g_v[(size_t)eg * 40 + 16 + tt] = (shvc * a2 + shs * b2 + cx2) * ISQ32;
            } else if (part < 28) {
                int o = 8 + (part - 20);
                float acc2 = 0.f;
#pragma unroll
                for (int i = 0; i < 16; i++) acc2 += Pe[44 + i] * Wt[320 + i * 16 + o];
#pragma unroll
                for (int i = 0; i < 8;  i++) acc2 += Pe[60 + i] * Wt[576 + i * 16 + o];
                if (active) g_v[(size_t)eg * 40 + o] = acc2 * ISQ24;

                int tt = 12 + (part - 20), o2 = tt / 3, c = tt - 3 * o2;
                float shs  = sm[SB_SH + e * 4];
                float shvc = sm[SB_SH + e * 4 + 1 + c];
                float a2 = 0.f, b2 = 0.f, cx2 = 0.f;
#pragma unroll
                for (int i = 0; i < 16; i++) a2  += Pe[i]              * Wt[704 + i * 8 + o2];
#pragma unroll
                for (int i = 0; i < 8;  i++) b2  += Pe[16 + c * 8 + i] * Wt[832 + i * 8 + o2];
#pragma unroll
                for (int i = 0; i < 8;  i++) cx2 += Pe[68 + c * 8 + i] * Wt[896 + i * 8 + o2];
                if (active) g_v[(size_t)eg * 40 + 16 + tt] = (shvc * a2 + shs * b2 + cx2) * ISQ32;
            } else {
                int tt = 20 + (part - 28), o2 = tt / 3, c = tt - 3 * o2;
                float shs  = sm[SB_SH + e * 4];
                float shvc = sm[SB_SH + e * 4 + 1 + c];
                float a2 = 0.f, b2 = 0.f, cx2 = 0.f;
#pragma unroll
                for (int i = 0; i < 16; i++) a2  += Pe[i]              * Wt[704 + i * 8 + o2];
#pragma unroll
                for (int i = 0; i < 8;  i++) b2  += Pe[16 + c * 8 + i] * Wt[832 + i * 8 + o2];
#pragma unroll
                for (int i = 0; i < 8;  i++) cx2 += Pe[68 + c * 8 + i] * Wt[896 + i * 8 + o2];
                if (active) g_v[(size_t)eg * 40 + 16 + tt] = (shvc * a2 + shs * b2 + cx2) * ISQ32;
            }
        }
        __syncthreads();

        // ---- dot(q[recv], k): one warp per edge ----
        {
            const int le = wid;
            const int eg = ebase + le;
            const bool active = (eg < E);
            const float* K  = sm + SB_K  + le * 21;
            const float* qr = sm + SB_QR + le * 21;
            float d = 0.f;
            {
                int term = lane;
                int i = term >> 3, j = term & 7;
                d += qr[i] * K[j] * sm[SB_WDS + i * 8 + j];
                term += 32; i = term >> 3; j = term & 7;
                d += qr[i] * K[j] * sm[SB_WDS + i * 8 + j];
            }
            if (lane < 16) {
                int i = lane >> 2, j = lane & 3;
                float s = qr[8 + i * 3 + 0] * K[8 + j * 3 + 0]
                        + qr[8 + i * 3 + 1] * K[8 + j * 3 + 1]
                        + qr[8 + i * 3 + 2] * K[8 + j * 3 + 2];
                d += s * sm[SB_WDV + i * 4 + j] * ISQ3;
            }
#pragma unroll
            for (int off = 16; off; off >>= 1) d += __shfl_xor_sync(0xffffffffu, d, off);
            if (lane == 0 && active) {
                d *= 0.11180339887498948f;
                float ex = expf(d);
                g_ex[eg] = ex;
                atomicAdd(&g_z[ixr[le]], ex);
            }
        }
        __syncthreads();
    }
}

// ---------------------------------------------------------------------------
__global__ void k_alpha(const int* __restrict__ eidx, int E)
{
    int e = blockIdx.x * blockDim.x + threadIdx.x;
    if (e >= E) return;
    g_ex[e] = sqrtf(__fdividef(g_ex[e], g_z[eidx[E + e]]));
}

// ---------------------------------------------------------------------------
__global__ void k_scatter(const int* __restrict__ eidx, float* __restrict__ out, int E)
{
    int idx = blockIdx.x * blockDim.x + threadIdx.x;
    int e = idx / 10, q = idx % 10;
    if (e >= E) return;
    int rcv = eidx[E + e];
    float a = g_ex[e];
    float4 v = *reinterpret_cast<const float4*>(&g_v[(size_t)e * 40 + q * 4]);
    float* dst = &out[(size_t)rcv * 40 + q * 4];
    asm volatile("red.global.add.v4.f32 [%0], {%1, %2, %3, %4};"
                 :: "l"(dst), "f"(a * v.x), "f"(a * v.y), "f"(a * v.z), "f"(a * v.w)
                 : "memory");
}

// ---------------------------------------------------------------------------
extern "C" void kernel_launch(void* const* d_in, const int* in_sizes, int n_in,
                              void* d_out, int out_size)
{
    const float* node_ft = (const float*)d_in[0];
    const int*   eidx    = (const int*)d_in[1];
    const float* edge_sh = (const float*)d_in[2];
    const float* edge_sc = (const float*)d_in[3];
    const float* wqs     = (const float*)d_in[4];
    const float* wqv     = (const float*)d_in[5];
    const float* fck_w1  = (const float*)d_in[6];
    const float* fck_w2  = (const float*)d_in[7];
    const float* fcv_w1  = (const float*)d_in[8];
    const float* fcv_w2  = (const float*)d_in[9];
    const float* wdot_s  = (const float*)d_in[10];
    const float* wdot_v  = (const float*)d_in[11];
    float* out = (float*)d_out;

    int N = in_sizes[0] / 40;
    int E = in_sizes[1] / 2;

    cudaFuncSetAttribute(k_edges, cudaFuncAttributeMaxDynamicSharedMemorySize, SMEM_BYTES);

    k_nodes<<<(N + 63) / 64, 64>>>(node_ft, wqs, wqv, out, N);
    k_edges<<<148, 1024, SMEM_BYTES>>>(node_ft, eidx, edge_sh, edge_sc,
                                       fck_w1, fck_w2, fcv_w1, fcv_w2,
                                       wdot_s, wdot_v, E);
    k_alpha<<<(E + 255) / 256, 256>>>(eidx, E);
    k_scatter<<<((long long)E * 10 + 255) / 256, 256>>>(eidx, out, E);
}

// round 16
// speedup vs baseline: 1.1275x; 1.1275x over previous
#include <cuda_runtime.h>
#include <math.h>
#include <stdint.h>

#define N_MAX 10000
#define E_MAX 100000

// Scratch (no cudaMalloc allowed)
__device__ float g_q[N_MAX * 20];
__device__ float g_z[N_MAX];
__device__ float g_ex[E_MAX];
__device__ float g_v[(size_t)E_MAX * 40];

__device__ __forceinline__ uint32_t cvt_tf32(float x) {
    uint32_t r; asm("cvt.rna.tf32.f32 %0, %1;" : "=r"(r) : "f"(x)); return r;
}

// ---------------------------------------------------------------------------
// Kernel 0: per-node q projection, zero z and out
// ---------------------------------------------------------------------------
__global__ void __launch_bounds__(64) k_nodes(const float* __restrict__ node_ft,
                        const float* __restrict__ wqs, const float* __restrict__ wqv,
                        float* __restrict__ out, int N)
{
    int n = blockIdx.x * blockDim.x + threadIdx.x;
    if (n >= N) return;
    const float* x = node_ft + (size_t)n * 40;
    float xs[16], xv[24];
#pragma unroll
    for (int i = 0; i < 16; i++) xs[i] = x[i];
#pragma unroll
    for (int i = 0; i < 24; i++) xv[i] = x[16 + i];
    const float s0 = 0.25f, s1 = 0.35355339059327373f;
    float q[20];
#pragma unroll
    for (int o = 0; o < 8; o++) {
        float a = 0.f;
#pragma unroll
        for (int i = 0; i < 16; i++) a += xs[i] * wqs[i * 8 + o];
        q[o] = a * s0;
    }
#pragma unroll
    for (int o = 0; o < 4; o++)
#pragma unroll
        for (int c = 0; c < 3; c++) {
            float a = 0.f;
#pragma unroll
            for (int i = 0; i < 8; i++) a += xv[i * 3 + c] * wqv[i * 4 + o];
            q[8 + o * 3 + c] = a * s1;
        }
#pragma unroll
    for (int i = 0; i < 20; i++) g_q[(size_t)n * 20 + i] = q[i];
    g_z[n] = 0.f;
    float4 z4 = make_float4(0.f, 0.f, 0.f, 0.f);
#pragma unroll
    for (int i = 0; i < 10; i++)
        *reinterpret_cast<float4*>(&out[(size_t)n * 40 + i * 4]) = z4;
}

// ---------------------------------------------------------------------------
// Main kernel (R12 base): persistent, 16 edges/tile, 512 threads,
//   mma.sync tf32 weight-gen, B fragments register-resident, gather prefetch,
//   uniform part-mapped epilogue WITH 4-way/2-way split accumulators (ILP).
// W tile: [e][col 0..959], pitch 970, column layout:
//   k: w1[16x8]@0 w2[8x8]@128 w3[16x4]@192 w4[8x4]@256 w5[8x4]@288
//   v(+320): w1[16x16]@0 w2[8x16]@256 w3[16x8]@384 w4[8x8]@512 w5[8x8]@576
// ---------------------------------------------------------------------------
#define SB_W    0          // 16 x 970
#define SB_HK   15520      // 16 x 33 (tf32 bits)
#define SB_HV   16048      // 16 x 33
#define SB_W1K  16576      // 512
#define SB_W1V  17088      // 512
#define SB_WDS  17600      // 64
#define SB_WDV  17664      // 16
#define SB_ES   17680      // 16 x 16
#define SB_SH   17936      // 16 x 4
#define SB_IX   18000      // 32 ints
#define SB_P    18032      // 16 x 97
#define SB_K    19584      // 16 x 21
#define SB_QR   19920      // 16 x 21
#define SMEM_FLOATS 20256
#define SMEM_BYTES (SMEM_FLOATS * 4)
#define WP 970

// 24-term dot helpers with split accumulators (stride-able weight index)
__device__ __forceinline__ float dot16_4(const float* __restrict__ p,
                                         const float* __restrict__ w, int stride) {
    float a0 = 0.f, a1 = 0.f, a2 = 0.f, a3 = 0.f;
#pragma unroll
    for (int i = 0; i < 4; i++) {
        a0 += p[i]      * w[i * stride];
        a1 += p[4 + i]  * w[(4 + i) * stride];
        a2 += p[8 + i]  * w[(8 + i) * stride];
        a3 += p[12 + i] * w[(12 + i) * stride];
    }
    return (a0 + a1) + (a2 + a3);
}
__device__ __forceinline__ float dot8_2(const float* __restrict__ p,
                                        const float* __restrict__ w, int stride) {
    float a0 = 0.f, a1 = 0.f;
#pragma unroll
    for (int i = 0; i < 4; i++) {
        a0 += p[i]     * w[i * stride];
        a1 += p[4 + i] * w[(4 + i) * stride];
    }
    return a0 + a1;
}

__global__ void __launch_bounds__(512, 1) k_edges(
    const float* __restrict__ node_ft,
    const int* __restrict__ eidx,
    const float* __restrict__ edge_sh,
    const float* __restrict__ edge_sc,
    const float* __restrict__ fck_w1,
    const float* __restrict__ fck_w2,
    const float* __restrict__ fcv_w1,
    const float* __restrict__ fcv_w2,
    const float* __restrict__ wdot_s,
    const float* __restrict__ wdot_v,
    int E)
{
    extern __shared__ float sm[];
    const int tid  = threadIdx.x;
    const int wid  = tid >> 5;
    const int lane = tid & 31;

    // ---- startup: B fragments -> registers (tile-invariant), W1/wdot -> smem
    const bool isv = (wid >= 5);
    const int tq = lane >> 2, tr = lane & 3;
    uint32_t bfrag[8][4][2];
    if (wid < 15) {
        const float* W2 = isv ? fcv_w2 : fck_w2;
        const int pitch = isv ? 640 : 320;
        const int nbase = isv ? (wid - 5) * 64 : wid * 64;
#pragma unroll
        for (int nc = 0; nc < 8; nc++) {
            int n0 = nbase + nc * 8;
#pragma unroll
            for (int kc = 0; kc < 4; kc++) {
                bfrag[nc][kc][0] = cvt_tf32(__ldg(&W2[(kc * 8 + tr) * pitch + n0 + tq]));
                bfrag[nc][kc][1] = cvt_tf32(__ldg(&W2[(kc * 8 + tr + 4) * pitch + n0 + tq]));
            }
        }
    }
    sm[SB_W1K + tid] = fck_w1[tid];
    sm[SB_W1V + tid] = fcv_w1[tid];
    if (tid < 64) sm[SB_WDS + tid] = wdot_s[tid];
    if (tid < 16) sm[SB_WDV + tid] = wdot_v[tid];
    __syncthreads();

    const float ISQ32 = 0.17677669529663687f;
    const float ISQ24 = 0.2041241452319315f;
    const float ISQ3  = 0.5773502691896258f;
    const float ISQ2  = 0.7071067811865476f;

    int* ixs = (int*)(sm + SB_IX);
    int* ixr = (int*)(sm + SB_IX + 16);
    const int ntiles = (E + 15) >> 4;

    for (int t = blockIdx.x; t < ntiles; t += 148) {
        const int ebase = t << 4;

        // ---- stage edge data ----
        if (tid < 256) {
            int e = tid >> 4, i = tid & 15;
            int eg = min(ebase + e, E - 1);
            sm[SB_ES + tid] = edge_sc[(size_t)eg * 16 + i];
        } else if (tid < 288) {
            int f = tid - 256;
            int e = f & 15;
            int eg = min(ebase + e, E - 1);
            if (f < 16) ixs[e] = eidx[eg];
            else        ixr[e] = eidx[E + eg];
        } else if (tid < 352) {
            int f = tid - 288;
            int eg = min(ebase + (f >> 2), E - 1);
            sm[SB_SH + f] = edge_sh[(size_t)eg * 4 + (f & 3)];
        }
        __syncthreads();

        // ---- P1 phase: prefetch nf gathers, hidden act (4-way acc), stage q ----
        const int e_pf = tid & 15, r_pf = tid >> 4;
        float nfv0 = 0.f, nfv1 = 0.f, nfv2 = 0.f;
        {
            const float* nf = node_ft + (size_t)ixs[e_pf] * 40;
            if (r_pf < 16) nfv0 = __ldg(&nf[r_pf]);
            else if (r_pf < 24) {
                int i = r_pf - 16;
                nfv0 = __ldg(&nf[16 + i * 3]);
                nfv1 = __ldg(&nf[17 + i * 3]);
                nfv2 = __ldg(&nf[18 + i * 3]);
            }
        }
        uint32_t* HK = (uint32_t*)(sm + SB_HK);
        uint32_t* HV = (uint32_t*)(sm + SB_HV);
#pragma unroll
        for (int s = 0; s < 2; s++) {
            int task = tid + s * 512;
            int e = task >> 6, jj = task & 63, j = jj & 31;
            const float* W1 = sm + ((jj < 32) ? SB_W1K : SB_W1V);
            const float* es = sm + SB_ES + e * 16;
            float a0 = 0.f, a1 = 0.f, a2 = 0.f, a3 = 0.f;
#pragma unroll
            for (int i = 0; i < 4; i++) {
                a0 += es[i]      * W1[i * 32 + j];
                a1 += es[4 + i]  * W1[(4 + i) * 32 + j];
                a2 += es[8 + i]  * W1[(8 + i) * 32 + j];
                a3 += es[12 + i] * W1[(12 + i) * 32 + j];
            }
            float a = ((a0 + a1) + (a2 + a3)) * 0.25f;
            float h = a / (1.f + expf(-a));
            uint32_t hb = cvt_tf32(h);
            if (jj < 32) HK[e * 33 + j] = hb;
            else         HV[e * 33 + j] = hb;
        }
        if (tid < 320) {
            int e2 = tid / 20, i = tid % 20;
            sm[SB_QR + e2 * 21 + i] = g_q[(size_t)ixr[e2] * 20 + i];
        }
        __syncthreads();

        // ---- P-feature build (prefetched regs) + P2 mma ----
        {
            float* Pe = sm + SB_P + e_pf * 97;
            if (r_pf < 16) {
                float shs = sm[SB_SH + e_pf * 4];
                Pe[r_pf]      = nfv0;
                Pe[44 + r_pf] = nfv0 * shs;
            } else if (r_pf < 24) {
                int i = r_pf - 16;
                float shv0 = sm[SB_SH + e_pf * 4 + 1];
                float shv1 = sm[SB_SH + e_pf * 4 + 2];
                float shv2 = sm[SB_SH + e_pf * 4 + 3];
                Pe[16 + 0 * 8 + i] = nfv0;
                Pe[16 + 1 * 8 + i] = nfv1;
                Pe[16 + 2 * 8 + i] = nfv2;
                Pe[60 + i] = (nfv0 * shv0 + nfv1 * shv1 + nfv2 * shv2) * ISQ3;
                Pe[68 + 0 * 8 + i] = (nfv1 * shv2 - nfv2 * shv1) * ISQ2;
                Pe[68 + 1 * 8 + i] = (nfv2 * shv0 - nfv0 * shv2) * ISQ2;
                Pe[68 + 2 * 8 + i] = (nfv0 * shv1 - nfv1 * shv0) * ISQ2;
            }
        }
        if (wid < 15) {
            const uint32_t* Hs = (const uint32_t*)(sm + (isv ? SB_HV : SB_HK));
            const int nbase = isv ? (wid - 5) * 64 : wid * 64;
            const int wcol0 = isv ? 320 + nbase : nbase;

            uint32_t a[4][4];
#pragma unroll
            for (int kc = 0; kc < 4; kc++) {
                int k0 = kc * 8;
                a[kc][0] = Hs[tq * 33 + k0 + tr];
                a[kc][1] = Hs[(tq + 8) * 33 + k0 + tr];
                a[kc][2] = Hs[tq * 33 + k0 + tr + 4];
                a[kc][3] = Hs[(tq + 8) * 33 + k0 + tr + 4];
            }
#pragma unroll
            for (int nc = 0; nc < 8; nc++) {
                float c0 = 0.f, c1 = 0.f, c2 = 0.f, c3 = 0.f;
#pragma unroll
                for (int kc = 0; kc < 4; kc++) {
                    asm volatile(
                        "mma.sync.aligned.m16n8k8.row.col.f32.tf32.tf32.f32 "
                        "{%0,%1,%2,%3}, {%4,%5,%6,%7}, {%8,%9}, {%0,%1,%2,%3};"
                        : "+f"(c0), "+f"(c1), "+f"(c2), "+f"(c3)
                        : "r"(a[kc][0]), "r"(a[kc][1]), "r"(a[kc][2]), "r"(a[kc][3]),
                          "r"(bfrag[nc][kc][0]), "r"(bfrag[nc][kc][1]));
                }
                float* W = sm + SB_W;
                int col = wcol0 + nc * 8 + 2 * tr;
                *reinterpret_cast<float2*>(&W[tq * WP + col]) =
                    make_float2(c0 * ISQ32, c1 * ISQ32);
                *reinterpret_cast<float2*>(&W[(tq + 8) * WP + col]) =
                    make_float2(c2 * ISQ32, c3 * ISQ32);
            }
        }
        __syncthreads();

        // ---- P3: uniform part-mapped epilogue, split accumulators ----
        {
            const int e = tid & 15, part = tid >> 4;
            const int eg = ebase + e;
            const bool active = (eg < E);
            const float* Pe = sm + SB_P + e * 97;
            const float* Wt = sm + SB_W + e * WP;

            if (part < 8) {
                int o = part;
                float acc = dot16_4(Pe + 44, Wt + o, 8)
                          + dot8_2(Pe + 60, Wt + 128 + o, 8);
                sm[SB_K + e * 21 + o] = acc * ISQ24;

                float acc2 = dot16_4(Pe + 44, Wt + 320 + o, 16)
                           + dot8_2(Pe + 60, Wt + 576 + o, 16);
                if (active) g_v[(size_t)eg * 40 + o] = acc2 * ISQ24;
            } else if (part < 20) {
                int tt = part - 8, o = tt / 3, c = tt - 3 * o;
                float shs  = sm[SB_SH + e * 4];
                float shvc = sm[SB_SH + e * 4 + 1 + c];
                float a  = dot16_4(Pe, Wt + 192 + o, 4);
                float b  = dot8_2(Pe + 16 + c * 8, Wt + 256 + o, 4);
                float cx = dot8_2(Pe + 68 + c * 8, Wt + 288 + o, 4);
                sm[SB_K + e * 21 + 8 + tt] = (shvc * a + shs * b + cx) * ISQ32;

                float a2  = dot16_4(Pe, Wt + 704 + o, 8);
                float b2  = dot8_2(Pe + 16 + c * 8, Wt + 832 + o, 8);
                float cx2 = dot8_2(Pe + 68 + c * 8, Wt + 896 + o, 8);
                if (active) g_v[(size_t)eg * 40 + 16 + tt] = (shvc * a2 + shs * b2 + cx2) * ISQ32;
            } else if (part < 28) {
                int o = 8 + (part - 20);
                float acc2 = dot16_4(Pe + 44, Wt + 320 + o, 16)
                           + dot8_2(Pe + 60, Wt + 576 + o, 16);
                if (active) g_v[(size_t)eg * 40 + o] = acc2 * ISQ24;

                int tt = 12 + (part - 20), o2 = tt / 3, c = tt - 3 * o2;
                float shs  = sm[SB_SH + e * 4];
                float shvc = sm[SB_SH + e * 4 + 1 + c];
                float a2  = dot16_4(Pe, Wt + 704 + o2, 8);
                float b2  = dot8_2(Pe + 16 + c * 8, Wt + 832 + o2, 8);
                float cx2 = dot8_2(Pe + 68 + c * 8, Wt + 896 + o2, 8);
                if (active) g_v[(size_t)eg * 40 + 16 + tt] = (shvc * a2 + shs * b2 + cx2) * ISQ32;
            } else {
                int tt = 20 + (part - 28), o2 = tt / 3, c = tt - 3 * o2;
                float shs  = sm[SB_SH + e * 4];
                float shvc = sm[SB_SH + e * 4 + 1 + c];
                float a2  = dot16_4(Pe, Wt + 704 + o2, 8);
                float b2  = dot8_2(Pe + 16 + c * 8, Wt + 832 + o2, 8);
                float cx2 = dot8_2(Pe + 68 + c * 8, Wt + 896 + o2, 8);
                if (active) g_v[(size_t)eg * 40 + 16 + tt] = (shvc * a2 + shs * b2 + cx2) * ISQ32;
            }
        }
        __syncthreads();

        // ---- dot(q[recv], k): warp per edge ----
        {
            const int le = wid;
            const int eg = ebase + le;
            const bool active = (eg < E);
            const float* K  = sm + SB_K  + le * 21;
            const float* qr = sm + SB_QR + le * 21;
            float d = 0.f;
            {
                int term = lane;
                int i = term >> 3, j = term & 7;
                d += qr[i] * K[j] * sm[SB_WDS + i * 8 + j];
                term += 32; i = term >> 3; j = term & 7;
                d += qr[i] * K[j] * sm[SB_WDS + i * 8 + j];
            }
            if (lane < 16) {
                int i = lane >> 2, j = lane & 3;
                float s = qr[8 + i * 3 + 0] * K[8 + j * 3 + 0]
                        + qr[8 + i * 3 + 1] * K[8 + j * 3 + 1]
                        + qr[8 + i * 3 + 2] * K[8 + j * 3 + 2];
                d += s * sm[SB_WDV + i * 4 + j] * ISQ3;
            }
#pragma unroll
            for (int off = 16; off; off >>= 1) d += __shfl_xor_sync(0xffffffffu, d, off);
            if (lane == 0 && active) {
                d *= 0.11180339887498948f;
                float ex = expf(d);
                g_ex[eg] = ex;
                atomicAdd(&g_z[ixr[le]], ex);
            }
        }
        __syncthreads();
    }
}

// ---------------------------------------------------------------------------
__global__ void k_alpha(const int* __restrict__ eidx, int E)
{
    int e = blockIdx.x * blockDim.x + threadIdx.x;
    if (e >= E) return;
    g_ex[e] = sqrtf(__fdividef(g_ex[e], g_z[eidx[E + e]]));
}

// ---------------------------------------------------------------------------
__global__ void k_scatter(const int* __restrict__ eidx, float* __restrict__ out, int E)
{
    int idx = blockIdx.x * blockDim.x + threadIdx.x;
    int e = idx / 10, q = idx % 10;
    if (e >= E) return;
    int rcv = eidx[E + e];
    float a = g_ex[e];
    float4 v = *reinterpret_cast<const float4*>(&g_v[(size_t)e * 40 + q * 4]);
    float* dst = &out[(size_t)rcv * 40 + q * 4];
    asm volatile("red.global.add.v4.f32 [%0], {%1, %2, %3, %4};"
                 :: "l"(dst), "f"(a * v.x), "f"(a * v.y), "f"(a * v.z), "f"(a * v.w)
                 : "memory");
}

// ---------------------------------------------------------------------------
extern "C" void kernel_launch(void* const* d_in, const int* in_sizes, int n_in,
                              void* d_out, int out_size)
{
    const float* node_ft = (const float*)d_in[0];
    const int*   eidx    = (const int*)d_in[1];
    const float* edge_sh = (const float*)d_in[2];
    const float* edge_sc = (const float*)d_in[3];
    const float* wqs     = (const float*)d_in[4];
    const float* wqv     = (const float*)d_in[5];
    const float* fck_w1  = (const float*)d_in[6];
    const float* fck_w2  = (const float*)d_in[7];
    const float* fcv_w1  = (const float*)d_in[8];
    const float* fcv_w2  = (const float*)d_in[9];
    const float* wdot_s  = (const float*)d_in[10];
    const float* wdot_v  = (const float*)d_in[11];
    float* out = (float*)d_out;

    int N = in_sizes[0] / 40;
    int E = in_sizes[1] / 2;

    cudaFuncSetAttribute(k_edges, cudaFuncAttributeMaxDynamicSharedMemorySize, SMEM_BYTES);

    k_nodes<<<(N + 63) / 64, 64>>>(node_ft, wqs, wqv, out, N);
    k_edges<<<148, 512, SMEM_BYTES>>>(node_ft, eidx, edge_sh, edge_sc,
                                      fck_w1, fck_w2, fcv_w1, fcv_w2,
                                      wdot_s, wdot_v, E);
    k_alpha<<<(E + 255) / 256, 256>>>(eidx, E);
    k_scatter<<<((long long)E * 10 + 255) / 256, 256>>>(eidx, out, E);
}

// round 17
// speedup vs baseline: 1.1485x; 1.0186x over previous
#include <cuda_runtime.h>
#include <math.h>
#include <stdint.h>

#define N_MAX 10000
#define E_MAX 100000

// Scratch (no cudaMalloc allowed)
__device__ float g_q[N_MAX * 20];
__device__ float g_z[N_MAX];
__device__ float g_ex[E_MAX];
__device__ float g_v[(size_t)E_MAX * 40];

__device__ __forceinline__ uint32_t cvt_tf32(float x) {
    uint32_t r; asm("cvt.rna.tf32.f32 %0, %1;" : "=r"(r) : "f"(x)); return r;
}

// ---------------------------------------------------------------------------
// Kernel 0: per-node q projection, zero z and out
// ---------------------------------------------------------------------------
__global__ void __launch_bounds__(64) k_nodes(const float* __restrict__ node_ft,
                        const float* __restrict__ wqs, const float* __restrict__ wqv,
                        float* __restrict__ out, int N)
{
    int n = blockIdx.x * blockDim.x + threadIdx.x;
    if (n >= N) return;
    const float* x = node_ft + (size_t)n * 40;
    float xs[16], xv[24];
#pragma unroll
    for (int i = 0; i < 16; i++) xs[i] = x[i];
#pragma unroll
    for (int i = 0; i < 24; i++) xv[i] = x[16 + i];
    const float s0 = 0.25f, s1 = 0.35355339059327373f;
    float q[20];
#pragma unroll
    for (int o = 0; o < 8; o++) {
        float a = 0.f;
#pragma unroll
        for (int i = 0; i < 16; i++) a += xs[i] * wqs[i * 8 + o];
        q[o] = a * s0;
    }
#pragma unroll
    for (int o = 0; o < 4; o++)
#pragma unroll
        for (int c = 0; c < 3; c++) {
            float a = 0.f;
#pragma unroll
            for (int i = 0; i < 8; i++) a += xv[i * 3 + c] * wqv[i * 4 + o];
            q[8 + o * 3 + c] = a * s1;
        }
#pragma unroll
    for (int i = 0; i < 20; i++) g_q[(size_t)n * 20 + i] = q[i];
    g_z[n] = 0.f;
    float4 z4 = make_float4(0.f, 0.f, 0.f, 0.f);
#pragma unroll
    for (int i = 0; i < 10; i++)
        *reinterpret_cast<float4*>(&out[(size_t)n * 40 + i * 4]) = z4;
}

// ---------------------------------------------------------------------------
// Main kernel (R16 base): persistent, 16 edges/tile, 512 threads,
//   mma.sync tf32 weight-gen, B fragments register-resident, gather prefetch,
//   uniform part-mapped epilogue with split accumulators, __expf fast math.
// W tile: [e][col 0..959], pitch 970, column layout:
//   k: w1[16x8]@0 w2[8x8]@128 w3[16x4]@192 w4[8x4]@256 w5[8x4]@288
//   v(+320): w1[16x16]@0 w2[8x16]@256 w3[16x8]@384 w4[8x8]@512 w5[8x8]@576
// ---------------------------------------------------------------------------
#define SB_W    0          // 16 x 970
#define SB_HK   15520      // 16 x 33 (tf32 bits)
#define SB_HV   16048      // 16 x 33
#define SB_W1K  16576      // 512
#define SB_W1V  17088      // 512
#define SB_WDS  17600      // 64
#define SB_WDV  17664      // 16
#define SB_ES   17680      // 16 x 16
#define SB_SH   17936      // 16 x 4
#define SB_IX   18000      // 32 ints
#define SB_P    18032      // 16 x 97
#define SB_K    19584      // 16 x 21
#define SB_QR   19920      // 16 x 21
#define SMEM_FLOATS 20256
#define SMEM_BYTES (SMEM_FLOATS * 4)
#define WP 970

// dot helpers with split accumulators (stride-able weight index)
__device__ __forceinline__ float dot16_4(const float* __restrict__ p,
                                         const float* __restrict__ w, int stride) {
    float a0 = 0.f, a1 = 0.f, a2 = 0.f, a3 = 0.f;
#pragma unroll
    for (int i = 0; i < 4; i++) {
        a0 += p[i]      * w[i * stride];
        a1 += p[4 + i]  * w[(4 + i) * stride];
        a2 += p[8 + i]  * w[(8 + i) * stride];
        a3 += p[12 + i] * w[(12 + i) * stride];
    }
    return (a0 + a1) + (a2 + a3);
}
__device__ __forceinline__ float dot8_2(const float* __restrict__ p,
                                        const float* __restrict__ w, int stride) {
    float a0 = 0.f, a1 = 0.f;
#pragma unroll
    for (int i = 0; i < 4; i++) {
        a0 += p[i]     * w[i * stride];
        a1 += p[4 + i] * w[(4 + i) * stride];
    }
    return a0 + a1;
}

__global__ void __launch_bounds__(512, 1) k_edges(
    const float* __restrict__ node_ft,
    const int* __restrict__ eidx,
    const float* __restrict__ edge_sh,
    const float* __restrict__ edge_sc,
    const float* __restrict__ fck_w1,
    const float* __restrict__ fck_w2,
    const float* __restrict__ fcv_w1,
    const float* __restrict__ fcv_w2,
    const float* __restrict__ wdot_s,
    const float* __restrict__ wdot_v,
    int E)
{
    extern __shared__ float sm[];
    const int tid  = threadIdx.x;
    const int wid  = tid >> 5;
    const int lane = tid & 31;

    // ---- startup: B fragments -> registers (tile-invariant), W1/wdot -> smem
    const bool isv = (wid >= 5);
    const int tq = lane >> 2, tr = lane & 3;
    uint32_t bfrag[8][4][2];
    if (wid < 15) {
        const float* W2 = isv ? fcv_w2 : fck_w2;
        const int pitch = isv ? 640 : 320;
        const int nbase = isv ? (wid - 5) * 64 : wid * 64;
#pragma unroll
        for (int nc = 0; nc < 8; nc++) {
            int n0 = nbase + nc * 8;
#pragma unroll
            for (int kc = 0; kc < 4; kc++) {
                bfrag[nc][kc][0] = cvt_tf32(__ldg(&W2[(kc * 8 + tr) * pitch + n0 + tq]));
                bfrag[nc][kc][1] = cvt_tf32(__ldg(&W2[(kc * 8 + tr + 4) * pitch + n0 + tq]));
            }
        }
    }
    sm[SB_W1K + tid] = fck_w1[tid];
    sm[SB_W1V + tid] = fcv_w1[tid];
    if (tid < 64) sm[SB_WDS + tid] = wdot_s[tid];
    if (tid < 16) sm[SB_WDV + tid] = wdot_v[tid];
    __syncthreads();

    const float ISQ32 = 0.17677669529663687f;
    const float ISQ24 = 0.2041241452319315f;
    const float ISQ3  = 0.5773502691896258f;
    const float ISQ2  = 0.7071067811865476f;

    int* ixs = (int*)(sm + SB_IX);
    int* ixr = (int*)(sm + SB_IX + 16);
    const int ntiles = (E + 15) >> 4;

    for (int t = blockIdx.x; t < ntiles; t += 148) {
        const int ebase = t << 4;

        // ---- stage edge data ----
        if (tid < 256) {
            int e = tid >> 4, i = tid & 15;
            int eg = min(ebase + e, E - 1);
            sm[SB_ES + tid] = edge_sc[(size_t)eg * 16 + i];
        } else if (tid < 288) {
            int f = tid - 256;
            int e = f & 15;
            int eg = min(ebase + e, E - 1);
            if (f < 16) ixs[e] = eidx[eg];
            else        ixr[e] = eidx[E + eg];
        } else if (tid < 352) {
            int f = tid - 288;
            int eg = min(ebase + (f >> 2), E - 1);
            sm[SB_SH + f] = edge_sh[(size_t)eg * 4 + (f & 3)];
        }
        __syncthreads();

        // ---- P1 phase: prefetch nf gathers, hidden act (4-way acc), stage q ----
        const int e_pf = tid & 15, r_pf = tid >> 4;
        float nfv0 = 0.f, nfv1 = 0.f, nfv2 = 0.f;
        {
            const float* nf = node_ft + (size_t)ixs[e_pf] * 40;
            if (r_pf < 16) nfv0 = __ldg(&nf[r_pf]);
            else if (r_pf < 24) {
                int i = r_pf - 16;
                nfv0 = __ldg(&nf[16 + i * 3]);
                nfv1 = __ldg(&nf[17 + i * 3]);
                nfv2 = __ldg(&nf[18 + i * 3]);
            }
        }
        uint32_t* HK = (uint32_t*)(sm + SB_HK);
        uint32_t* HV = (uint32_t*)(sm + SB_HV);
#pragma unroll
        for (int s = 0; s < 2; s++) {
            int task = tid + s * 512;
            int e = task >> 6, jj = task & 63, j = jj & 31;
            const float* W1 = sm + ((jj < 32) ? SB_W1K : SB_W1V);
            const float* es = sm + SB_ES + e * 16;
            float a0 = 0.f, a1 = 0.f, a2 = 0.f, a3 = 0.f;
#pragma unroll
            for (int i = 0; i < 4; i++) {
                a0 += es[i]      * W1[i * 32 + j];
                a1 += es[4 + i]  * W1[(4 + i) * 32 + j];
                a2 += es[8 + i]  * W1[(8 + i) * 32 + j];
                a3 += es[12 + i] * W1[(12 + i) * 32 + j];
            }
            float a = ((a0 + a1) + (a2 + a3)) * 0.25f;
            float h = __fdividef(a, 1.f + __expf(-a));
            uint32_t hb = cvt_tf32(h);
            if (jj < 32) HK[e * 33 + j] = hb;
            else         HV[e * 33 + j] = hb;
        }
        if (tid < 320) {
            int e2 = tid / 20, i = tid % 20;
            sm[SB_QR + e2 * 21 + i] = g_q[(size_t)ixr[e2] * 20 + i];
        }
        __syncthreads();

        // ---- P-feature build (prefetched regs) + P2 mma ----
        {
            float* Pe = sm + SB_P + e_pf * 97;
            if (r_pf < 16) {
                float shs = sm[SB_SH + e_pf * 4];
                Pe[r_pf]      = nfv0;
                Pe[44 + r_pf] = nfv0 * shs;
            } else if (r_pf < 24) {
                int i = r_pf - 16;
                float shv0 = sm[SB_SH + e_pf * 4 + 1];
                float shv1 = sm[SB_SH + e_pf * 4 + 2];
                float shv2 = sm[SB_SH + e_pf * 4 + 3];
                Pe[16 + 0 * 8 + i] = nfv0;
                Pe[16 + 1 * 8 + i] = nfv1;
                Pe[16 + 2 * 8 + i] = nfv2;
                Pe[60 + i] = (nfv0 * shv0 + nfv1 * shv1 + nfv2 * shv2) * ISQ3;
                Pe[68 + 0 * 8 + i] = (nfv1 * shv2 - nfv2 * shv1) * ISQ2;
                Pe[68 + 1 * 8 + i] = (nfv2 * shv0 - nfv0 * shv2) * ISQ2;
                Pe[68 + 2 * 8 + i] = (nfv0 * shv1 - nfv1 * shv0) * ISQ2;
            }
        }
        if (wid < 15) {
            const uint32_t* Hs = (const uint32_t*)(sm + (isv ? SB_HV : SB_HK));
            const int nbase = isv ? (wid - 5) * 64 : wid * 64;
            const int wcol0 = isv ? 320 + nbase : nbase;

            uint32_t a[4][4];
#pragma unroll
            for (int kc = 0; kc < 4; kc++) {
                int k0 = kc * 8;
                a[kc][0] = Hs[tq * 33 + k0 + tr];
                a[kc][1] = Hs[(tq + 8) * 33 + k0 + tr];
                a[kc][2] = Hs[tq * 33 + k0 + tr + 4];
                a[kc][3] = Hs[(tq + 8) * 33 + k0 + tr + 4];
            }
#pragma unroll
            for (int nc = 0; nc < 8; nc++) {
                float c0 = 0.f, c1 = 0.f, c2 = 0.f, c3 = 0.f;
#pragma unroll
                for (int kc = 0; kc < 4; kc++) {
                    asm volatile(
                        "mma.sync.aligned.m16n8k8.row.col.f32.tf32.tf32.f32 "
                        "{%0,%1,%2,%3}, {%4,%5,%6,%7}, {%8,%9}, {%0,%1,%2,%3};"
                        : "+f"(c0), "+f"(c1), "+f"(c2), "+f"(c3)
                        : "r"(a[kc][0]), "r"(a[kc][1]), "r"(a[kc][2]), "r"(a[kc][3]),
                          "r"(bfrag[nc][kc][0]), "r"(bfrag[nc][kc][1]));
                }
                float* W = sm + SB_W;
                int col = wcol0 + nc * 8 + 2 * tr;
                *reinterpret_cast<float2*>(&W[tq * WP + col]) =
                    make_float2(c0 * ISQ32, c1 * ISQ32);
                *reinterpret_cast<float2*>(&W[(tq + 8) * WP + col]) =
                    make_float2(c2 * ISQ32, c3 * ISQ32);
            }
        }
        __syncthreads();

        // ---- P3: uniform part-mapped epilogue, split accumulators ----
        {
            const int e = tid & 15, part = tid >> 4;
            const int eg = ebase + e;
            const bool active = (eg < E);
            const float* Pe = sm + SB_P + e * 97;
            const float* Wt = sm + SB_W + e * WP;

            if (part < 8) {
                int o = part;
                float acc = dot16_4(Pe + 44, Wt + o, 8)
                          + dot8_2(Pe + 60, Wt + 128 + o, 8);
                sm[SB_K + e * 21 + o] = acc * ISQ24;

                float acc2 = dot16_4(Pe + 44, Wt + 320 + o, 16)
                           + dot8_2(Pe + 60, Wt + 576 + o, 16);
                if (active) g_v[(size_t)eg * 40 + o] = acc2 * ISQ24;
            } else if (part < 20) {
                int tt = part - 8, o = tt / 3, c = tt - 3 * o;
                float shs  = sm[SB_SH + e * 4];
                float shvc = sm[SB_SH + e * 4 + 1 + c];
                float a  = dot16_4(Pe, Wt + 192 + o, 4);
                float b  = dot8_2(Pe + 16 + c * 8, Wt + 256 + o, 4);
                float cx = dot8_2(Pe + 68 + c * 8, Wt + 288 + o, 4);
                sm[SB_K + e * 21 + 8 + tt] = (shvc * a + shs * b + cx) * ISQ32;

                float a2  = dot16_4(Pe, Wt + 704 + o, 8);
                float b2  = dot8_2(Pe + 16 + c * 8, Wt + 832 + o, 8);
                float cx2 = dot8_2(Pe + 68 + c * 8, Wt + 896 + o, 8);
                if (active) g_v[(size_t)eg * 40 + 16 + tt] = (shvc * a2 + shs * b2 + cx2) * ISQ32;
            } else if (part < 28) {
                int o = 8 + (part - 20);
                float acc2 = dot16_4(Pe + 44, Wt + 320 + o, 16)
                           + dot8_2(Pe + 60, Wt + 576 + o, 16);
                if (active) g_v[(size_t)eg * 40 + o] = acc2 * ISQ24;

                int tt = 12 + (part - 20), o2 = tt / 3, c = tt - 3 * o2;
                float shs  = sm[SB_SH + e * 4];
                float shvc = sm[SB_SH + e * 4 + 1 + c];
                float a2  = dot16_4(Pe, Wt + 704 + o2, 8);
                float b2  = dot8_2(Pe + 16 + c * 8, Wt + 832 + o2, 8);
                float cx2 = dot8_2(Pe + 68 + c * 8, Wt + 896 + o2, 8);
                if (active) g_v[(size_t)eg * 40 + 16 + tt] = (shvc * a2 + shs * b2 + cx2) * ISQ32;
            } else {
                int tt = 20 + (part - 28), o2 = tt / 3, c = tt - 3 * o2;
                float shs  = sm[SB_SH + e * 4];
                float shvc = sm[SB_SH + e * 4 + 1 + c];
                float a2  = dot16_4(Pe, Wt + 704 + o2, 8);
                float b2  = dot8_2(Pe + 16 + c * 8, Wt + 832 + o2, 8);
                float cx2 = dot8_2(Pe + 68 + c * 8, Wt + 896 + o2, 8);
                if (active) g_v[(size_t)eg * 40 + 16 + tt] = (shvc * a2 + shs * b2 + cx2) * ISQ32;
            }
        }
        __syncthreads();

        // ---- dot(q[recv], k): warp per edge ----
        {
            const int le = wid;
            const int eg = ebase + le;
            const bool active = (eg < E);
            const float* K  = sm + SB_K  + le * 21;
            const float* qr = sm + SB_QR + le * 21;
            float d = 0.f;
            {
                int term = lane;
                int i = term >> 3, j = term & 7;
                d += qr[i] * K[j] * sm[SB_WDS + i * 8 + j];
                term += 32; i = term >> 3; j = term & 7;
                d += qr[i] * K[j] * sm[SB_WDS + i * 8 + j];
            }
            if (lane < 16) {
                int i = lane >> 2, j = lane & 3;
                float s = qr[8 + i * 3 + 0] * K[8 + j * 3 + 0]
                        + qr[8 + i * 3 + 1] * K[8 + j * 3 + 1]
                        + qr[8 + i * 3 + 2] * K[8 + j * 3 + 2];
                d += s * sm[SB_WDV + i * 4 + j] * ISQ3;
            }
#pragma unroll
            for (int off = 16; off; off >>= 1) d += __shfl_xor_sync(0xffffffffu, d, off);
            if (lane == 0 && active) {
                d *= 0.11180339887498948f;
                float ex = __expf(d);
                g_ex[eg] = ex;
                atomicAdd(&g_z[ixr[le]], ex);
            }
        }
        __syncthreads();
    }
}

// ---------------------------------------------------------------------------
// Scatter (fused alpha): a = sqrt(ex/z[rcv]); out[rcv] += a * v  (red.v4)
// ---------------------------------------------------------------------------
__global__ void k_scatter(const int* __restrict__ eidx, float* __restrict__ out, int E)
{
    int idx = blockIdx.x * blockDim.x + threadIdx.x;
    int e = idx / 10, q = idx % 10;
    if (e >= E) return;
    int rcv = eidx[E + e];
    float a = sqrtf(__fdividef(g_ex[e], g_z[rcv]));
    float4 v = *reinterpret_cast<const float4*>(&g_v[(size_t)e * 40 + q * 4]);
    float* dst = &out[(size_t)rcv * 40 + q * 4];
    asm volatile("red.global.add.v4.f32 [%0], {%1, %2, %3, %4};"
                 :: "l"(dst), "f"(a * v.x), "f"(a * v.y), "f"(a * v.z), "f"(a * v.w)
                 : "memory");
}

// ---------------------------------------------------------------------------
extern "C" void kernel_launch(void* const* d_in, const int* in_sizes, int n_in,
                              void* d_out, int out_size)
{
    const float* node_ft = (const float*)d_in[0];
    const int*   eidx    = (const int*)d_in[1];
    const float* edge_sh = (const float*)d_in[2];
    const float* edge_sc = (const float*)d_in[3];
    const float* wqs     = (const float*)d_in[4];
    const float* wqv     = (const float*)d_in[5];
    const float* fck_w1  = (const float*)d_in[6];
    const float* fck_w2  = (const float*)d_in[7];
    const float* fcv_w1  = (const float*)d_in[8];
    const float* fcv_w2  = (const float*)d_in[9];
    const float* wdot_s  = (const float*)d_in[10];
    const float* wdot_v  = (const float*)d_in[11];
    float* out = (float*)d_out;

    int N = in_sizes[0] / 40;
    int E = in_sizes[1] / 2;

    cudaFuncSetAttribute(k_edges, cudaFuncAttributeMaxDynamicSharedMemorySize, SMEM_BYTES);

    k_nodes<<<(N + 63) / 64, 64>>>(node_ft, wqs, wqv, out, N);
    k_edges<<<148, 512, SMEM_BYTES>>>(node_ft, eidx, edge_sh, edge_sc,
                                      fck_w1, fck_w2, fcv_w1, fcv_w2,
                                      wdot_s, wdot_v, E);
    k_scatter<<<((long long)E * 10 + 255) / 256, 256>>>(eidx, out, E);
}